// round 14
// baseline (speedup 1.0000x reference)
#include <cuda_runtime.h>
#include <cuda_bf16.h>
#include <cstdint>

// Problem constants
#define N_APP  100000
#define N_ATTR 50000
#define D      128
#define NB_ATTR 391   // ceil(50000/128)
#define NB_APP  782   // ceil(100000/128)
#define N_TOT  250000 // concatenated node space: [attr(rel0) | app(rel1) | app(rel2)]
#define BASE1  50000
#define BASE2  150000
#define EMAX   500000
#define NBLK_SCAN 245 // ceil(250000/1024)

// ---------------- device scratch (no allocation allowed) ----------------
// pre-split aggregated neighbor features: per node 512B = [kh0: hi128|lo128][kh1: hi128|lo128],
// bf16, pre-scaled by 1/max(deg,1), chunk-XOR swizzled by (node&7) — the GEMM's A smem layout.
__device__ uint2 g_s0[(size_t)N_ATTR * 64];
__device__ uint2 g_s1[(size_t)N_APP * 64];
__device__ uint2 g_s2[(size_t)N_APP * 64];
__device__ float g_pattr[(size_t)N_ATTR * 2];
__device__ float g_papp[(size_t)N_APP * 4];
__device__ int   g_cnt[N_TOT];
__device__ int   g_row[N_TOT];
__device__ int   g_bsum[256];
__device__ int   g_scan_ctr;
__device__ uint2 g_pack[3 * EMAX];   // CSR-ordered (src, ew-bits) records
__device__ float g_bsum1[D];       // b1[1]+b1[2]
__device__ float g_Wn1c[D * 2];    // Wneigh2[1] @ Wc
__device__ float g_Wapp4[D * 4];   // cols 0..1: (Wself2[1]+Wself2[2])@Wc ; cols 2..3: Wneigh2[2]@Wc
__device__ float g_bce[2];         // (b2[1]+b2[2])@Wc + bc
// bf16 weight tiles, merged hi/lo row-local layout:
// tile m (0..4), half kh (0..1): 32KB block = 128 rows x 256B; row n: [hi 128B | lo 128B],
// hi chunk c at ((c ^ (n&7))<<4).
__device__ uint2 g_Bt[5 * 2 * 4096];

// ---------------- PTX helpers ----------------
__device__ __forceinline__ uint32_t smem_u32(const void* p) {
    uint32_t a;
    asm("{ .reg .u64 t; cvta.to.shared.u64 t, %1; cvt.u32.u64 %0, t; }" : "=r"(a) : "l"(p));
    return a;
}
__device__ __forceinline__ void ldsm_x4(uint32_t* r, uint32_t addr) {
    asm volatile("ldmatrix.sync.aligned.m8n8.x4.shared.b16 {%0,%1,%2,%3}, [%4];"
                 : "=r"(r[0]), "=r"(r[1]), "=r"(r[2]), "=r"(r[3]) : "r"(addr));
}
__device__ __forceinline__ void mma_bf16(float* c, const uint32_t* a, uint32_t b0, uint32_t b1) {
    asm volatile("mma.sync.aligned.m16n8k16.row.col.f32.bf16.bf16.f32 "
                 "{%0,%1,%2,%3}, {%4,%5,%6,%7}, {%8,%9}, {%0,%1,%2,%3};"
                 : "+f"(c[0]), "+f"(c[1]), "+f"(c[2]), "+f"(c[3])
                 : "r"(a[0]), "r"(a[1]), "r"(a[2]), "r"(a[3]), "r"(b0), "r"(b1));
}
__device__ __forceinline__ void cp_async16(uint32_t dst, const void* src) {
    asm volatile("cp.async.cg.shared.global [%0], [%1], 16;" :: "r"(dst), "l"(src) : "memory");
}
__device__ __forceinline__ void sts_u2(uint32_t addr, uint32_t a, uint32_t b) {
    asm volatile("st.shared.v2.b32 [%0], {%1,%2};" :: "r"(addr), "r"(a), "r"(b));
}
__device__ __forceinline__ void sts_zero16(uint32_t addr) {
    asm volatile("st.shared.v4.b32 [%0], {%1,%1,%1,%1};" :: "r"(addr), "r"(0u));
}
__device__ __forceinline__ float4 lds_f4(uint32_t addr) {
    float4 v;
    asm volatile("ld.shared.v4.f32 {%0,%1,%2,%3}, [%4];"
                 : "=f"(v.x), "=f"(v.y), "=f"(v.z), "=f"(v.w) : "r"(addr));
    return v;
}
__device__ __forceinline__ uint32_t bf2u(__nv_bfloat162 v) {
    return *reinterpret_cast<uint32_t*>(&v);
}

// ---------------- fused count + weight prep (independent work, one launch) ----------------
// blocks [0, nblk): edge counting; blocks [nblk, nblk+5): weight tile m; block nblk+5: small prep
__global__ void count_prep_kernel(
    const int* __restrict__ d0, const int* __restrict__ d1, const int* __restrict__ d2, int E,
    int nblk,
    const float* __restrict__ Wself1, const float* __restrict__ Wneigh1,
    const float* __restrict__ b1,
    const float* __restrict__ Wself2, const float* __restrict__ Wneigh2,
    const float* __restrict__ b2,
    const float* __restrict__ Wc, const float* __restrict__ bc)
{
    int b = blockIdx.x;
    int tid = threadIdx.x;
    if (b < nblk) {
        int i = b * 256 + tid;
        if (i < E)           atomicAdd(&g_cnt[d0[i]], 1);
        else if (i < 2 * E)  atomicAdd(&g_cnt[BASE1 + d1[i - E]], 1);
        else if (i < 3 * E)  atomicAdd(&g_cnt[BASE2 + d2[i - 2 * E]], 1);
        return;
    }
    if (b < nblk + 5) {
        // weight tiles: transpose + hi/lo bf16 split + merged row-local layout
        int m = b - nblk;
        for (int idx = tid; idx < 4096; idx += 256) {
            int n = idx >> 5;
            int cg = idx & 31;
            int k0 = cg * 4;
            float w[4];
            #pragma unroll
            for (int i = 0; i < 4; i++) {
                int k = k0 + i;
                float v;
                if      (m == 0) v = Wself1[k * D + n];
                else if (m == 1) v = Wneigh1[k * D + n];
                else if (m == 2) v = Wself1[16384 + k * D + n] + Wself1[32768 + k * D + n];
                else if (m == 3) v = Wneigh1[16384 + k * D + n];
                else             v = Wneigh1[32768 + k * D + n];
                w[i] = v;
            }
            __nv_bfloat162 h01 = __floats2bfloat162_rn(w[0], w[1]);
            __nv_bfloat162 h23 = __floats2bfloat162_rn(w[2], w[3]);
            float2 f01 = __bfloat1622float2(h01), f23 = __bfloat1622float2(h23);
            __nv_bfloat162 l01 = __floats2bfloat162_rn(w[0] - f01.x, w[1] - f01.y);
            __nv_bfloat162 l23 = __floats2bfloat162_rn(w[2] - f23.x, w[3] - f23.y);
            int half = cg >> 4;
            int cgi  = cg & 15;
            char* base = (char*)g_Bt + ((size_t)(m * 2 + half)) * 32768 + (size_t)n * 256;
            uint32_t sw = (uint32_t)((((cgi >> 1) ^ (n & 7)) << 4) + ((cgi & 1) << 3));
            *(uint2*)(base + sw)       = make_uint2(bf2u(h01), bf2u(h23));
            *(uint2*)(base + 128 + sw) = make_uint2(bf2u(l01), bf2u(l23));
        }
        return;
    }
    // small-weight prep (+ scan counter reset)
    if (tid == 0) g_scan_ctr = 0;
    if (tid < D) g_bsum1[tid] = b1[128 + tid] + b1[256 + tid];
    {
        int i = tid >> 1, j = tid & 1;
        float s_sc = 0.f, s_n2 = 0.f, s_n1 = 0.f;
        #pragma unroll 4
        for (int l = 0; l < D; l++) {
            float wc = Wc[l * 2 + j];
            s_sc += (Wself2[16384 + i * D + l] + Wself2[32768 + i * D + l]) * wc;
            s_n2 += Wneigh2[32768 + i * D + l] * wc;
            s_n1 += Wneigh2[16384 + i * D + l] * wc;
        }
        g_Wapp4[i * 4 + j]     = s_sc;
        g_Wapp4[i * 4 + 2 + j] = s_n2;
        g_Wn1c[i * 2 + j]      = s_n1;
    }
    if (tid < 2) {
        float s = bc[tid];
        for (int l = 0; l < D; l++) s += (b2[128 + l] + b2[256 + l]) * Wc[l * 2 + tid];
        g_bce[tid] = s;
    }
}

// ---------------- fused scan: per-block scan + last-block global scan of block sums ----------------
__global__ void scan_kernel()
{
    __shared__ int sh[8];
    __shared__ int is_last;
    int b = blockIdx.x, t = threadIdx.x;
    int base = b * 1024 + t * 4;
    int v[4];
    #pragma unroll
    for (int i = 0; i < 4; i++) v[i] = (base + i < N_TOT) ? g_cnt[base + i] : 0;
    int local = v[0] + v[1] + v[2] + v[3];
    int lane = t & 31, w = t >> 5;
    int inc = local;
    #pragma unroll
    for (int o = 1; o < 32; o <<= 1) {
        int x = __shfl_up_sync(0xffffffffu, inc, o);
        if (lane >= o) inc += x;
    }
    if (lane == 31) sh[w] = inc;
    __syncthreads();
    if (t == 0) {
        int run = 0;
        #pragma unroll
        for (int i = 0; i < 8; i++) { int x = sh[i]; sh[i] = run; run += x; }
        g_bsum[b] = run;
    }
    __syncthreads();
    int run = sh[w] + inc - local;
    #pragma unroll
    for (int i = 0; i < 4; i++) {
        if (base + i < N_TOT) g_row[base + i] = run;
        run += v[i];
    }
    // last block scans the block sums (exclusive) in place
    __threadfence();
    if (t == 0) {
        int done = atomicAdd(&g_scan_ctr, 1);
        is_last = (done == NBLK_SCAN - 1) ? 1 : 0;
    }
    __syncthreads();
    if (!is_last) return;
    int bv = (t < NBLK_SCAN) ? g_bsum[t] : 0;
    int binc = bv;
    #pragma unroll
    for (int o = 1; o < 32; o <<= 1) {
        int x = __shfl_up_sync(0xffffffffu, binc, o);
        if (lane >= o) binc += x;
    }
    if (lane == 31) sh[w] = binc;
    __syncthreads();
    if (t == 0) {
        int run2 = 0;
        #pragma unroll
        for (int i = 0; i < 8; i++) { int x = sh[i]; sh[i] = run2; run2 += x; }
    }
    __syncthreads();
    if (t < NBLK_SCAN) g_bsum[t] = sh[w] + binc - bv;
}

// fill bumps g_row in place; consumers recover start = row - cnt + bsum[blk]
__global__ void fill_kernel(const int* __restrict__ d0, const int* __restrict__ d1,
                            const int* __restrict__ d2,
                            const int* __restrict__ s0, const int* __restrict__ s1,
                            const int* __restrict__ s2,
                            const float* __restrict__ w0, const float* __restrict__ w1,
                            const float* __restrict__ w2, int E)
{
    int i = blockIdx.x * 256 + threadIdx.x;
    int gidx; uint2 rec;
    if (i < E)          { gidx = d0[i];                rec = make_uint2((uint32_t)s0[i], __float_as_uint(w0[i])); }
    else if (i < 2 * E) { int e = i - E;     gidx = BASE1 + d1[e]; rec = make_uint2((uint32_t)s1[e], __float_as_uint(w1[e])); }
    else if (i < 3 * E) { int e = i - 2 * E; gidx = BASE2 + d2[e]; rec = make_uint2((uint32_t)s2[e], __float_as_uint(w2[e])); }
    else return;
    int pos = atomicAdd(&g_row[gidx], 1) + g_bsum[gidx >> 10];
    g_pack[pos] = rec;
}

// ---------------- CSR aggregation: warp per node, emits pre-scaled hi/lo bf16 split ----------------
__global__ void __launch_bounds__(256) agg_kernel(
    const float4* __restrict__ x_app, const float4* __restrict__ x_attr)
{
    int gw = (blockIdx.x * 256 + threadIdx.x) >> 5;
    int lane = threadIdx.x & 31;
    if (gw >= N_TOT) return;
    const float4* feat; char* out; int v;
    if (gw < BASE1)      { feat = x_app;  out = (char*)g_s0; v = gw; }
    else if (gw < BASE2) { feat = x_attr; out = (char*)g_s1; v = gw - BASE1; }
    else                 { feat = x_app;  out = (char*)g_s2; v = gw - BASE2; }
    int n = g_cnt[gw];
    int start = g_row[gw] - n + g_bsum[gw >> 10];
    float4 acc = make_float4(0.f, 0.f, 0.f, 0.f);
    for (int c = 0; c < n; c += 32) {
        int m = n - c; if (m > 32) m = 32;
        int s = 0; float w = 0.f;
        if (lane < m) {
            uint2 rec = __ldg(&g_pack[start + c + lane]);
            s = (int)rec.x;
            w = __uint_as_float(rec.y);
        }
        #pragma unroll 4
        for (int j = 0; j < m; j++) {
            int sj   = __shfl_sync(0xffffffffu, s, j);
            float wj = __shfl_sync(0xffffffffu, w, j);
            float4 t = feat[(size_t)sj * 32 + lane];
            acc.x += wj * t.x; acc.y += wj * t.y; acc.z += wj * t.z; acc.w += wj * t.w;
        }
    }
    float sc = 1.f / fmaxf((float)n, 1.f);
    float x0 = acc.x * sc, x1 = acc.y * sc, x2 = acc.z * sc, x3 = acc.w * sc;
    __nv_bfloat162 h01 = __floats2bfloat162_rn(x0, x1);
    __nv_bfloat162 h23 = __floats2bfloat162_rn(x2, x3);
    float2 f01 = __bfloat1622float2(h01), f23 = __bfloat1622float2(h23);
    __nv_bfloat162 l01 = __floats2bfloat162_rn(x0 - f01.x, x1 - f01.y);
    __nv_bfloat162 l23 = __floats2bfloat162_rn(x2 - f23.x, x3 - f23.y);
    int kh = lane >> 4;
    int cg = lane & 15;
    uint32_t sw = (uint32_t)((((cg >> 1) ^ (v & 7)) << 4) + ((cg & 1) << 3));
    char* base = out + (size_t)v * 512 + kh * 256 + sw;
    *(uint2*)base         = make_uint2(bf2u(h01), bf2u(h23));
    *(uint2*)(base + 128) = make_uint2(bf2u(l01), bf2u(l23));
}

// ---------------- merged tensor-core GEMM + fused layer-2 projection ----------------
#define OFF_A0    0
#define OFF_A1    32768
#define OFF_B     65536
#define OFF_BIAS  98304
#define OFF_PW    98816
#define GEMM_SMEM 100864

__global__ void __launch_bounds__(256, 2) gemm_fused_all(
    const float* __restrict__ x_attr, const float* __restrict__ x_app,
    const char* __restrict__ s0, const char* __restrict__ s1, const char* __restrict__ s2,
    const float* __restrict__ b1, const float* __restrict__ bsum1,
    const float* __restrict__ Wn1c, const float* __restrict__ Wapp4,
    const uint2* __restrict__ Bt,
    float* __restrict__ pattr, float* __restrict__ papp)
{
    extern __shared__ __align__(1024) char smem[];
    const uint32_t sb = smem_u32(smem);
    const int tid = threadIdx.x;
    const int wid = tid >> 5, lane = tid & 31;
    const int mw = wid >> 1;
    const int nw = wid & 1;

    const bool is_app = (int)blockIdx.x >= NB_ATTR;
    const int bid = is_app ? (int)blockIdx.x - NB_ATTR : (int)blockIdx.x;
    const int m0 = bid * 128;
    const int M = is_app ? N_APP : N_ATTR;
    const int nstg = is_app ? 6 : 4;

    const float* Aself = is_app ? x_app : x_attr;
    const char* Asplit[3];
    int tile0;
    if (is_app) { Asplit[0] = nullptr; Asplit[1] = s1; Asplit[2] = s2; tile0 = 2; }
    else        { Asplit[0] = nullptr; Asplit[1] = s0; Asplit[2] = nullptr; tile0 = 0; }
    const float* bias = is_app ? bsum1 : b1;

    if (tid < 128) ((float*)(smem + OFF_BIAS))[tid] = bias[tid];
    for (int idx = tid; idx < 512; idx += 256) {
        int r = idx >> 2, c = idx & 3;
        ((float*)(smem + OFF_PW))[idx] = is_app ? Wapp4[idx] : (c < 2 ? Wn1c[r * 2 + c] : 0.f);
    }

    float acc[2][8][4];
    #pragma unroll
    for (int i = 0; i < 2; i++)
        #pragma unroll
        for (int j = 0; j < 8; j++)
            #pragma unroll
            for (int q = 0; q < 4; q++) acc[i][j][q] = 0.f;

    const int a_rowl = lane & 15;
    const int a_half = lane >> 4;
    const int b_rowl = (lane & 7) + ((lane >> 4) << 3);
    const int b_half = (lane >> 3) & 1;

    const uint32_t bufA[2] = { sb + OFF_A0, sb + OFF_A1 };

    auto prefetchA = [&](int s, uint32_t buf) {
        int blk = s >> 1, kh = s & 1;
        if (blk == 0) {
            #pragma unroll
            for (int i = 0; i < 8; i++) {
                int g = tid + i * 256;
                int r = g >> 4, cg = g & 15;
                int grow = m0 + r;
                uint32_t dst = buf + (uint32_t)g * 16u;
                if (grow < M) cp_async16(dst, Aself + (size_t)grow * 128 + kh * 64 + cg * 4);
                else          sts_zero16(dst);
            }
        } else {
            const char* S = Asplit[blk];
            #pragma unroll
            for (int i = 0; i < 8; i++) {
                int g = tid + i * 256;
                int r = g >> 4, cg = g & 15;
                int grow = m0 + r;
                uint32_t dst = buf + (uint32_t)g * 16u;
                if (grow < M) cp_async16(dst, S + (size_t)grow * 512 + kh * 256 + cg * 16);
                else          sts_zero16(dst);
            }
        }
        asm volatile("cp.async.commit_group;" ::: "memory");
    };

    prefetchA(0, bufA[0]);

    for (int s = 0; s < nstg; s++) {
        const int p = s & 1;
        __syncthreads();
        {
            int kh = s & 1;
            const char* bsrc = (const char*)Bt + ((size_t)(tile0 + (s >> 1)) * 2 + kh) * 32768;
            #pragma unroll
            for (int i = 0; i < 8; i++) {
                uint32_t t = (uint32_t)(tid + i * 256) * 16u;
                cp_async16(sb + OFF_B + t, bsrc + t);
            }
            asm volatile("cp.async.commit_group;" ::: "memory");
        }
        if (s < 2) {
            // self stage: raw fp32 -> in-place hi/lo bf16 convert
            asm volatile("cp.async.wait_group 1;" ::: "memory");
            #pragma unroll
            for (int h = 0; h < 2; h++) {       // disjoint row halves: 0-63 / 64-127
                float4 raw[4];
                #pragma unroll
                for (int i = 0; i < 4; i++) {
                    int g = h * 1024 + tid + i * 256;
                    raw[i] = lds_f4(bufA[p] + (uint32_t)g * 16u);
                }
                __syncthreads();
                #pragma unroll
                for (int i = 0; i < 4; i++) {
                    int g = h * 1024 + tid + i * 256;
                    int r = g >> 4, cg = g & 15;
                    __nv_bfloat162 h01 = __floats2bfloat162_rn(raw[i].x, raw[i].y);
                    __nv_bfloat162 h23 = __floats2bfloat162_rn(raw[i].z, raw[i].w);
                    float2 f01 = __bfloat1622float2(h01), f23 = __bfloat1622float2(h23);
                    __nv_bfloat162 l01 = __floats2bfloat162_rn(raw[i].x - f01.x, raw[i].y - f01.y);
                    __nv_bfloat162 l23 = __floats2bfloat162_rn(raw[i].z - f23.x, raw[i].w - f23.y);
                    uint32_t base = bufA[p] + (uint32_t)r * 256u
                                  + (uint32_t)((((cg >> 1) ^ (r & 7)) << 4) + ((cg & 1) << 3));
                    sts_u2(base,        bf2u(h01), bf2u(h23));
                    sts_u2(base + 128u, bf2u(l01), bf2u(l23));
                }
            }
        }
        asm volatile("cp.async.wait_group 0;" ::: "memory");
        __syncthreads();
        if (s + 1 < nstg) prefetchA(s + 1, bufA[1 - p]);

        #pragma unroll
        for (int ks = 0; ks < 4; ks++) {
            uint32_t ah[2][4], al[2][4];
            #pragma unroll
            for (int mt = 0; mt < 2; mt++) {
                int r = mw * 32 + mt * 16 + a_rowl;
                uint32_t base = bufA[p] + (uint32_t)r * 256u
                              + (uint32_t)(((2 * ks + a_half) ^ (r & 7)) << 4);
                ldsm_x4(ah[mt], base);
                ldsm_x4(al[mt], base + 128u);
            }
            #pragma unroll
            for (int nb = 0; nb < 4; nb++) {
                int r = nw * 64 + nb * 16 + b_rowl;
                uint32_t base = sb + OFF_B + (uint32_t)r * 256u
                              + (uint32_t)(((2 * ks + b_half) ^ (r & 7)) << 4);
                uint32_t bh[4], bl[4];
                ldsm_x4(bh, base);
                ldsm_x4(bl, base + 128u);
                #pragma unroll
                for (int mt = 0; mt < 2; mt++) {
                    mma_bf16(acc[mt][nb * 2 + 0], ah[mt], bh[0], bh[1]);
                    mma_bf16(acc[mt][nb * 2 + 1], ah[mt], bh[2], bh[3]);
                    mma_bf16(acc[mt][nb * 2 + 0], ah[mt], bl[0], bl[1]);
                    mma_bf16(acc[mt][nb * 2 + 1], ah[mt], bl[2], bl[3]);
                    mma_bf16(acc[mt][nb * 2 + 0], al[mt], bh[0], bh[1]);
                    mma_bf16(acc[mt][nb * 2 + 1], al[mt], bh[2], bh[3]);
                }
            }
        }
    }

    // ---- epilogue: relu(acc+bias) @ Wproj, shfl-reduce, plain store (rows disjoint per block) ----
    const float* bias_s = (const float*)(smem + OFF_BIAS);
    const float* pw = (const float*)(smem + OFF_PW);
    #pragma unroll
    for (int mt = 0; mt < 2; mt++) {
        float p0[4] = {0.f, 0.f, 0.f, 0.f};
        float p1[4] = {0.f, 0.f, 0.f, 0.f};
        #pragma unroll
        for (int nt = 0; nt < 8; nt++) {
            int col = nw * 64 + nt * 8 + (lane & 3) * 2;
            float b0 = bias_s[col], b1v = bias_s[col + 1];
            float vx = fmaxf(acc[mt][nt][0] + b0, 0.f);
            float vy = fmaxf(acc[mt][nt][1] + b1v, 0.f);
            float vz = fmaxf(acc[mt][nt][2] + b0, 0.f);
            float vw = fmaxf(acc[mt][nt][3] + b1v, 0.f);
            #pragma unroll
            for (int c = 0; c < 4; c++) {
                p0[c] += vx * pw[col * 4 + c] + vy * pw[(col + 1) * 4 + c];
                p1[c] += vz * pw[col * 4 + c] + vw * pw[(col + 1) * 4 + c];
            }
        }
        // reduce across the 2 N-warps (nw) and 4 lane-quads holding the same rows:
        // lanes with same (lane>>2) across quads... rows are per (mw,mt,lane>>2); columns split
        // across nw and lane&3. Sum over lane&3 via xor 1,2; sum over nw via global add-free trick:
        // instead store partials and combine — but nw covers DIFFERENT columns of h (outer sum),
        // so both nw halves contribute to the same projection. Reduce nw pairs via shared? Use
        // xor on wid? Simplest: shfl covers lanes only; combine nw via atomic-free two-step in smem.
        #pragma unroll
        for (int c = 0; c < 4; c++) {
            p0[c] += __shfl_xor_sync(0xffffffffu, p0[c], 1);
            p0[c] += __shfl_xor_sync(0xffffffffu, p0[c], 2);
            p1[c] += __shfl_xor_sync(0xffffffffu, p1[c], 1);
            p1[c] += __shfl_xor_sync(0xffffffffu, p1[c], 2);
        }
        if ((lane & 3) == 0) {
            int r0l = mw * 32 + mt * 16 + (lane >> 2);
            float* buf = (float*)(smem + OFF_A0);      // reuse A buffer for cross-warp combine
            if (nw == 0) {
                #pragma unroll
                for (int c = 0; c < 4; c++) buf[r0l * 4 + c] = p0[c];
                #pragma unroll
                for (int c = 0; c < 4; c++) buf[(r0l + 8) * 4 + c] = p1[c];
            }
        }
        __syncthreads();
        if ((lane & 3) == 0 && nw == 1) {
            int r0l = mw * 32 + mt * 16 + (lane >> 2);
            float* buf = (float*)(smem + OFF_A0);
            int r0 = m0 + r0l;
            if (r0 < M) {
                float q0 = buf[r0l * 4 + 0] + p0[0];
                float q1 = buf[r0l * 4 + 1] + p0[1];
                float q2 = buf[r0l * 4 + 2] + p0[2];
                float q3 = buf[r0l * 4 + 3] + p0[3];
                if (is_app) *(float4*)(papp + (size_t)r0 * 4) = make_float4(q0, q1, q2, q3);
                else        *(float2*)(pattr + (size_t)r0 * 2) = make_float2(q0, q1);
            }
            if (r0 + 8 < M) {
                float q0 = buf[(r0l + 8) * 4 + 0] + p1[0];
                float q1 = buf[(r0l + 8) * 4 + 1] + p1[1];
                float q2 = buf[(r0l + 8) * 4 + 2] + p1[2];
                float q3 = buf[(r0l + 8) * 4 + 3] + p1[3];
                if (is_app) *(float4*)(papp + (size_t)(r0 + 8) * 4) = make_float4(q0, q1, q2, q3);
                else        *(float2*)(pattr + (size_t)(r0 + 8) * 2) = make_float2(q0, q1);
            }
        }
        __syncthreads();
    }
}

// ---------------- fused layer-2 aggregation + finalize (packed CSR, serial per node) ----------------
__global__ void __launch_bounds__(256) final_kernel(float* __restrict__ out)
{
    int v = blockIdx.x * 256 + threadIdx.x;
    if (v >= N_APP) return;
    int g1 = BASE1 + v, g2 = BASE2 + v;
    int n1 = g_cnt[g1];
    int s1 = g_row[g1] - n1 + g_bsum[g1 >> 10];
    float a0 = 0.f, a1 = 0.f;
    #pragma unroll 4
    for (int i = 0; i < n1; i++) {
        uint2 rec = __ldg(&g_pack[s1 + i]);
        int sp = (int)rec.x;
        float w = __uint_as_float(rec.y);
        a0 += w * g_pattr[sp * 2 + 0];
        a1 += w * g_pattr[sp * 2 + 1];
    }
    int n2 = g_cnt[g2];
    int s2 = g_row[g2] - n2 + g_bsum[g2 >> 10];
    float b0 = 0.f, b1v = 0.f;
    #pragma unroll 4
    for (int i = 0; i < n2; i++) {
        uint2 rec = __ldg(&g_pack[s2 + i]);
        int sp = (int)rec.x;
        float w = __uint_as_float(rec.y);
        b0  += w * g_papp[sp * 4 + 2];
        b1v += w * g_papp[sp * 4 + 3];
    }
    float i1 = 1.f / fmaxf((float)n1, 1.f);
    float i2 = 1.f / fmaxf((float)n2, 1.f);
    out[v * 2 + 0] = g_papp[v * 4 + 0] + a0 * i1 + b0 * i2 + g_bce[0];
    out[v * 2 + 1] = g_papp[v * 4 + 1] + a1 * i1 + b1v * i2 + g_bce[1];
}

// ---------------- launch ----------------
extern "C" void kernel_launch(void* const* d_in, const int* in_sizes, int n_in,
                              void* d_out, int out_size)
{
    const float* x_app   = (const float*)d_in[0];
    const float* x_attr  = (const float*)d_in[1];
    const float* ew0     = (const float*)d_in[2];
    const float* ew1     = (const float*)d_in[3];
    const float* ew2     = (const float*)d_in[4];
    const float* Wself1  = (const float*)d_in[5];
    const float* Wneigh1 = (const float*)d_in[6];
    const float* b1      = (const float*)d_in[7];
    const float* Wself2  = (const float*)d_in[8];
    const float* Wneigh2 = (const float*)d_in[9];
    const float* b2      = (const float*)d_in[10];
    const float* Wc      = (const float*)d_in[11];
    const float* bc      = (const float*)d_in[12];
    const int* src0 = (const int*)d_in[13];
    const int* dst0 = (const int*)d_in[14];
    const int* src1 = (const int*)d_in[15];
    const int* dst1 = (const int*)d_in[16];
    const int* src2 = (const int*)d_in[17];
    const int* dst2 = (const int*)d_in[18];
    float* out = (float*)d_out;
    const int E = in_sizes[2];

    float *pattr, *papp, *bsum1, *Wn1c, *Wapp4;
    int *cnt;
    uint2 *Bt, *s0, *s1, *s2;
    cudaGetSymbolAddress((void**)&s0, g_s0);
    cudaGetSymbolAddress((void**)&s1, g_s1);
    cudaGetSymbolAddress((void**)&s2, g_s2);
    cudaGetSymbolAddress((void**)&pattr, g_pattr);
    cudaGetSymbolAddress((void**)&papp, g_papp);
    cudaGetSymbolAddress((void**)&cnt, g_cnt);
    cudaGetSymbolAddress((void**)&bsum1, g_bsum1);
    cudaGetSymbolAddress((void**)&Wn1c, g_Wn1c);
    cudaGetSymbolAddress((void**)&Wapp4, g_Wapp4);
    cudaGetSymbolAddress((void**)&Bt, g_Bt);

    cudaFuncSetAttribute(gemm_fused_all, cudaFuncAttributeMaxDynamicSharedMemorySize, GEMM_SMEM);

    cudaMemsetAsync(cnt, 0, sizeof(g_cnt), 0);

    // fused: edge counting + weight prep (+ scan counter reset) in one launch
    int eb3 = (3 * E + 255) / 256;
    count_prep_kernel<<<eb3 + 6, 256>>>(dst0, dst1, dst2, E, eb3,
                                        Wself1, Wneigh1, b1, Wself2, Wneigh2, b2, Wc, bc);
    scan_kernel<<<NBLK_SCAN, 256>>>();
    fill_kernel<<<eb3, 256>>>(dst0, dst1, dst2, src0, src1, src2, ew0, ew1, ew2, E);

    // layer-1 aggregation: contiguous packed reads, pre-scaled pre-split bf16 output
    agg_kernel<<<(N_TOT * 32 + 255) / 256, 256>>>(
        (const float4*)x_app, (const float4*)x_attr);

    // merged layer-1 GEMMs + fused layer-2 projection (plain-store epilogue)
    gemm_fused_all<<<NB_ATTR + NB_APP, 256, GEMM_SMEM>>>(
        x_attr, x_app, (const char*)s0, (const char*)s1, (const char*)s2,
        b1, bsum1, Wn1c, Wapp4, Bt, pattr, papp);

    // fused layer-2 aggregation + classify
    final_kernel<<<(N_APP + 255) / 256, 256>>>(out);
}

// round 15
// speedup vs baseline: 1.0423x; 1.0423x over previous
#include <cuda_runtime.h>
#include <cuda_bf16.h>
#include <cstdint>

// Problem constants
#define N_APP  100000
#define N_ATTR 50000
#define D      128
#define NB_ATTR 391   // ceil(50000/128)
#define NB_APP  782   // ceil(100000/128)
#define N_TOT  250000 // concatenated node space: [attr(rel0) | app(rel1) | app(rel2)]
#define BASE1  50000
#define BASE2  150000
#define EMAX   500000
#define NBLK_SCAN 245 // ceil(250000/1024)

// ---------------- device scratch (no allocation allowed) ----------------
// pre-split aggregated neighbor features: per node 512B = [kh0: hi128|lo128][kh1: hi128|lo128],
// bf16, pre-scaled by 1/max(deg,1), chunk-XOR swizzled by (node&7) — the GEMM's A smem layout.
__device__ uint2 g_s0[(size_t)N_ATTR * 64];
__device__ uint2 g_s1[(size_t)N_APP * 64];
__device__ uint2 g_s2[(size_t)N_APP * 64];
__device__ float g_pattr[(size_t)N_ATTR * 2];
__device__ float g_papp[(size_t)N_APP * 4];
__device__ int2  g_meta[N_TOT];     // .x = cnt, .y = row (excl. within-block; fill bumps)
__device__ int   g_bsum[256];
__device__ int   g_scan_ctr;
__device__ uint2 g_pack[3 * EMAX];   // CSR-ordered (src, ew-bits) records
__device__ float g_bsum1[D];       // b1[1]+b1[2]
__device__ float g_Wn1c[D * 2];    // Wneigh2[1] @ Wc
__device__ float g_Wapp4[D * 4];   // cols 0..1: (Wself2[1]+Wself2[2])@Wc ; cols 2..3: Wneigh2[2]@Wc
__device__ float g_bce[2];         // (b2[1]+b2[2])@Wc + bc
// bf16 weight tiles, merged hi/lo row-local layout:
// tile m (0..4), half kh (0..1): 32KB block = 128 rows x 256B; row n: [hi 128B | lo 128B],
// hi chunk c at ((c ^ (n&7))<<4).
__device__ uint2 g_Bt[5 * 2 * 4096];

// ---------------- PTX helpers ----------------
__device__ __forceinline__ uint32_t smem_u32(const void* p) {
    uint32_t a;
    asm("{ .reg .u64 t; cvta.to.shared.u64 t, %1; cvt.u32.u64 %0, t; }" : "=r"(a) : "l"(p));
    return a;
}
__device__ __forceinline__ void ldsm_x4(uint32_t* r, uint32_t addr) {
    asm volatile("ldmatrix.sync.aligned.m8n8.x4.shared.b16 {%0,%1,%2,%3}, [%4];"
                 : "=r"(r[0]), "=r"(r[1]), "=r"(r[2]), "=r"(r[3]) : "r"(addr));
}
__device__ __forceinline__ void mma_bf16(float* c, const uint32_t* a, uint32_t b0, uint32_t b1) {
    asm volatile("mma.sync.aligned.m16n8k16.row.col.f32.bf16.bf16.f32 "
                 "{%0,%1,%2,%3}, {%4,%5,%6,%7}, {%8,%9}, {%0,%1,%2,%3};"
                 : "+f"(c[0]), "+f"(c[1]), "+f"(c[2]), "+f"(c[3])
                 : "r"(a[0]), "r"(a[1]), "r"(a[2]), "r"(a[3]), "r"(b0), "r"(b1));
}
__device__ __forceinline__ void cp_async16(uint32_t dst, const void* src) {
    asm volatile("cp.async.cg.shared.global [%0], [%1], 16;" :: "r"(dst), "l"(src) : "memory");
}
__device__ __forceinline__ void sts_u2(uint32_t addr, uint32_t a, uint32_t b) {
    asm volatile("st.shared.v2.b32 [%0], {%1,%2};" :: "r"(addr), "r"(a), "r"(b));
}
__device__ __forceinline__ void sts_zero16(uint32_t addr) {
    asm volatile("st.shared.v4.b32 [%0], {%1,%1,%1,%1};" :: "r"(addr), "r"(0u));
}
__device__ __forceinline__ float4 lds_f4(uint32_t addr) {
    float4 v;
    asm volatile("ld.shared.v4.f32 {%0,%1,%2,%3}, [%4];"
                 : "=f"(v.x), "=f"(v.y), "=f"(v.z), "=f"(v.w) : "r"(addr));
    return v;
}
__device__ __forceinline__ uint32_t bf2u(__nv_bfloat162 v) {
    return *reinterpret_cast<uint32_t*>(&v);
}

// ---------------- fused count + weight prep (independent work, one launch) ----------------
// blocks [0, nblk): edge counting; blocks [nblk, nblk+5): weight tile m; block nblk+5: small prep
__global__ void count_prep_kernel(
    const int* __restrict__ d0, const int* __restrict__ d1, const int* __restrict__ d2, int E,
    int nblk,
    const float* __restrict__ Wself1, const float* __restrict__ Wneigh1,
    const float* __restrict__ b1,
    const float* __restrict__ Wself2, const float* __restrict__ Wneigh2,
    const float* __restrict__ b2,
    const float* __restrict__ Wc, const float* __restrict__ bc)
{
    int b = blockIdx.x;
    int tid = threadIdx.x;
    if (b < nblk) {
        int i = b * 256 + tid;
        if (i < E)           atomicAdd(&g_meta[d0[i]].x, 1);
        else if (i < 2 * E)  atomicAdd(&g_meta[BASE1 + d1[i - E]].x, 1);
        else if (i < 3 * E)  atomicAdd(&g_meta[BASE2 + d2[i - 2 * E]].x, 1);
        return;
    }
    if (b < nblk + 5) {
        // weight tiles: transpose + hi/lo bf16 split + merged row-local layout
        int m = b - nblk;
        for (int idx = tid; idx < 4096; idx += 256) {
            int n = idx >> 5;
            int cg = idx & 31;
            int k0 = cg * 4;
            float w[4];
            #pragma unroll
            for (int i = 0; i < 4; i++) {
                int k = k0 + i;
                float v;
                if      (m == 0) v = Wself1[k * D + n];
                else if (m == 1) v = Wneigh1[k * D + n];
                else if (m == 2) v = Wself1[16384 + k * D + n] + Wself1[32768 + k * D + n];
                else if (m == 3) v = Wneigh1[16384 + k * D + n];
                else             v = Wneigh1[32768 + k * D + n];
                w[i] = v;
            }
            __nv_bfloat162 h01 = __floats2bfloat162_rn(w[0], w[1]);
            __nv_bfloat162 h23 = __floats2bfloat162_rn(w[2], w[3]);
            float2 f01 = __bfloat1622float2(h01), f23 = __bfloat1622float2(h23);
            __nv_bfloat162 l01 = __floats2bfloat162_rn(w[0] - f01.x, w[1] - f01.y);
            __nv_bfloat162 l23 = __floats2bfloat162_rn(w[2] - f23.x, w[3] - f23.y);
            int half = cg >> 4;
            int cgi  = cg & 15;
            char* base = (char*)g_Bt + ((size_t)(m * 2 + half)) * 32768 + (size_t)n * 256;
            uint32_t sw = (uint32_t)((((cgi >> 1) ^ (n & 7)) << 4) + ((cgi & 1) << 3));
            *(uint2*)(base + sw)       = make_uint2(bf2u(h01), bf2u(h23));
            *(uint2*)(base + 128 + sw) = make_uint2(bf2u(l01), bf2u(l23));
        }
        return;
    }
    // small-weight prep (+ scan counter reset)
    if (tid == 0) g_scan_ctr = 0;
    if (tid < D) g_bsum1[tid] = b1[128 + tid] + b1[256 + tid];
    {
        int i = tid >> 1, j = tid & 1;
        float s_sc = 0.f, s_n2 = 0.f, s_n1 = 0.f;
        #pragma unroll 4
        for (int l = 0; l < D; l++) {
            float wc = Wc[l * 2 + j];
            s_sc += (Wself2[16384 + i * D + l] + Wself2[32768 + i * D + l]) * wc;
            s_n2 += Wneigh2[32768 + i * D + l] * wc;
            s_n1 += Wneigh2[16384 + i * D + l] * wc;
        }
        g_Wapp4[i * 4 + j]     = s_sc;
        g_Wapp4[i * 4 + 2 + j] = s_n2;
        g_Wn1c[i * 2 + j]      = s_n1;
    }
    if (tid < 2) {
        float s = bc[tid];
        for (int l = 0; l < D; l++) s += (b2[128 + l] + b2[256 + l]) * Wc[l * 2 + tid];
        g_bce[tid] = s;
    }
}

// ---------------- fused scan: per-block scan + last-block global scan of block sums ----------------
__global__ void scan_kernel()
{
    __shared__ int sh[8];
    __shared__ int is_last;
    int b = blockIdx.x, t = threadIdx.x;
    int base = b * 1024 + t * 4;
    int v[4];
    #pragma unroll
    for (int i = 0; i < 4; i++) v[i] = (base + i < N_TOT) ? g_meta[base + i].x : 0;
    int local = v[0] + v[1] + v[2] + v[3];
    int lane = t & 31, w = t >> 5;
    int inc = local;
    #pragma unroll
    for (int o = 1; o < 32; o <<= 1) {
        int x = __shfl_up_sync(0xffffffffu, inc, o);
        if (lane >= o) inc += x;
    }
    if (lane == 31) sh[w] = inc;
    __syncthreads();
    if (t == 0) {
        int run = 0;
        #pragma unroll
        for (int i = 0; i < 8; i++) { int x = sh[i]; sh[i] = run; run += x; }
        g_bsum[b] = run;
    }
    __syncthreads();
    int run = sh[w] + inc - local;
    #pragma unroll
    for (int i = 0; i < 4; i++) {
        if (base + i < N_TOT) g_meta[base + i].y = run;
        run += v[i];
    }
    // last block scans the block sums (exclusive) in place
    __threadfence();
    if (t == 0) {
        int done = atomicAdd(&g_scan_ctr, 1);
        is_last = (done == NBLK_SCAN - 1) ? 1 : 0;
    }
    __syncthreads();
    if (!is_last) return;
    int bv = (t < NBLK_SCAN) ? g_bsum[t] : 0;
    int binc = bv;
    #pragma unroll
    for (int o = 1; o < 32; o <<= 1) {
        int x = __shfl_up_sync(0xffffffffu, binc, o);
        if (lane >= o) binc += x;
    }
    if (lane == 31) sh[w] = binc;
    __syncthreads();
    if (t == 0) {
        int run2 = 0;
        #pragma unroll
        for (int i = 0; i < 8; i++) { int x = sh[i]; sh[i] = run2; run2 += x; }
    }
    __syncthreads();
    if (t < NBLK_SCAN) g_bsum[t] = sh[w] + binc - bv;
}

// fill bumps g_meta[.].y in place; consumers recover start = y - cnt + bsum[blk]
__global__ void fill_kernel(const int* __restrict__ d0, const int* __restrict__ d1,
                            const int* __restrict__ d2,
                            const int* __restrict__ s0, const int* __restrict__ s1,
                            const int* __restrict__ s2,
                            const float* __restrict__ w0, const float* __restrict__ w1,
                            const float* __restrict__ w2, int E)
{
    int i = blockIdx.x * 256 + threadIdx.x;
    int gidx; uint2 rec;
    if (i < E)          { gidx = d0[i];                rec = make_uint2((uint32_t)s0[i], __float_as_uint(w0[i])); }
    else if (i < 2 * E) { int e = i - E;     gidx = BASE1 + d1[e]; rec = make_uint2((uint32_t)s1[e], __float_as_uint(w1[e])); }
    else if (i < 3 * E) { int e = i - 2 * E; gidx = BASE2 + d2[e]; rec = make_uint2((uint32_t)s2[e], __float_as_uint(w2[e])); }
    else return;
    int pos = atomicAdd(&g_meta[gidx].y, 1) + g_bsum[gidx >> 10];
    g_pack[pos] = rec;
}

// ---------------- CSR aggregation: warp per node, single 8B meta load, pre-split bf16 out ----------------
__global__ void __launch_bounds__(256) agg_kernel(
    const float4* __restrict__ x_app, const float4* __restrict__ x_attr)
{
    int gw = (blockIdx.x * 256 + threadIdx.x) >> 5;
    int lane = threadIdx.x & 31;
    if (gw >= N_TOT) return;
    const float4* feat; char* out; int v;
    if (gw < BASE1)      { feat = x_app;  out = (char*)g_s0; v = gw; }
    else if (gw < BASE2) { feat = x_attr; out = (char*)g_s1; v = gw - BASE1; }
    else                 { feat = x_app;  out = (char*)g_s2; v = gw - BASE2; }
    int2 meta = __ldg(&g_meta[gw]);
    int n = meta.x;
    int start = meta.y - n + g_bsum[gw >> 10];
    float4 acc = make_float4(0.f, 0.f, 0.f, 0.f);
    for (int c = 0; c < n; c += 32) {
        int m = n - c; if (m > 32) m = 32;
        int s = 0; float w = 0.f;
        if (lane < m) {
            uint2 rec = __ldg(&g_pack[start + c + lane]);
            s = (int)rec.x;
            w = __uint_as_float(rec.y);
        }
        #pragma unroll 4
        for (int j = 0; j < m; j++) {
            int sj   = __shfl_sync(0xffffffffu, s, j);
            float wj = __shfl_sync(0xffffffffu, w, j);
            float4 t = feat[(size_t)sj * 32 + lane];
            acc.x += wj * t.x; acc.y += wj * t.y; acc.z += wj * t.z; acc.w += wj * t.w;
        }
    }
    float sc = 1.f / fmaxf((float)n, 1.f);
    float x0 = acc.x * sc, x1 = acc.y * sc, x2 = acc.z * sc, x3 = acc.w * sc;
    __nv_bfloat162 h01 = __floats2bfloat162_rn(x0, x1);
    __nv_bfloat162 h23 = __floats2bfloat162_rn(x2, x3);
    float2 f01 = __bfloat1622float2(h01), f23 = __bfloat1622float2(h23);
    __nv_bfloat162 l01 = __floats2bfloat162_rn(x0 - f01.x, x1 - f01.y);
    __nv_bfloat162 l23 = __floats2bfloat162_rn(x2 - f23.x, x3 - f23.y);
    int kh = lane >> 4;
    int cg = lane & 15;
    uint32_t sw = (uint32_t)((((cg >> 1) ^ (v & 7)) << 4) + ((cg & 1) << 3));
    char* base = out + (size_t)v * 512 + kh * 256 + sw;
    *(uint2*)base         = make_uint2(bf2u(h01), bf2u(h23));
    *(uint2*)(base + 128) = make_uint2(bf2u(l01), bf2u(l23));
}

// ---------------- merged tensor-core GEMM + fused layer-2 projection ----------------
#define OFF_A0    0
#define OFF_A1    32768
#define OFF_B     65536
#define OFF_BIAS  98304
#define OFF_PW    98816
#define GEMM_SMEM 100864

__global__ void __launch_bounds__(256, 2) gemm_fused_all(
    const float* __restrict__ x_attr, const float* __restrict__ x_app,
    const char* __restrict__ s0, const char* __restrict__ s1, const char* __restrict__ s2,
    const float* __restrict__ b1, const float* __restrict__ bsum1,
    const float* __restrict__ Wn1c, const float* __restrict__ Wapp4,
    const uint2* __restrict__ Bt,
    float* __restrict__ pattr, float* __restrict__ papp)
{
    extern __shared__ __align__(1024) char smem[];
    const uint32_t sb = smem_u32(smem);
    const int tid = threadIdx.x;
    const int wid = tid >> 5, lane = tid & 31;
    const int mw = wid >> 1;
    const int nw = wid & 1;

    const bool is_app = (int)blockIdx.x >= NB_ATTR;
    const int bid = is_app ? (int)blockIdx.x - NB_ATTR : (int)blockIdx.x;
    const int m0 = bid * 128;
    const int M = is_app ? N_APP : N_ATTR;
    const int nstg = is_app ? 6 : 4;

    const float* Aself = is_app ? x_app : x_attr;
    const char* Asplit[3];
    int tile0;
    if (is_app) { Asplit[0] = nullptr; Asplit[1] = s1; Asplit[2] = s2; tile0 = 2; }
    else        { Asplit[0] = nullptr; Asplit[1] = s0; Asplit[2] = nullptr; tile0 = 0; }
    const float* bias = is_app ? bsum1 : b1;

    if (tid < 128) ((float*)(smem + OFF_BIAS))[tid] = bias[tid];
    for (int idx = tid; idx < 512; idx += 256) {
        int r = idx >> 2, c = idx & 3;
        ((float*)(smem + OFF_PW))[idx] = is_app ? Wapp4[idx] : (c < 2 ? Wn1c[r * 2 + c] : 0.f);
    }

    float acc[2][8][4];
    #pragma unroll
    for (int i = 0; i < 2; i++)
        #pragma unroll
        for (int j = 0; j < 8; j++)
            #pragma unroll
            for (int q = 0; q < 4; q++) acc[i][j][q] = 0.f;

    const int a_rowl = lane & 15;
    const int a_half = lane >> 4;
    const int b_rowl = (lane & 7) + ((lane >> 4) << 3);
    const int b_half = (lane >> 3) & 1;

    const uint32_t bufA[2] = { sb + OFF_A0, sb + OFF_A1 };

    auto prefetchA = [&](int s, uint32_t buf) {
        int blk = s >> 1, kh = s & 1;
        if (blk == 0) {
            #pragma unroll
            for (int i = 0; i < 8; i++) {
                int g = tid + i * 256;
                int r = g >> 4, cg = g & 15;
                int grow = m0 + r;
                uint32_t dst = buf + (uint32_t)g * 16u;
                if (grow < M) cp_async16(dst, Aself + (size_t)grow * 128 + kh * 64 + cg * 4);
                else          sts_zero16(dst);
            }
        } else {
            const char* S = Asplit[blk];
            #pragma unroll
            for (int i = 0; i < 8; i++) {
                int g = tid + i * 256;
                int r = g >> 4, cg = g & 15;
                int grow = m0 + r;
                uint32_t dst = buf + (uint32_t)g * 16u;
                if (grow < M) cp_async16(dst, S + (size_t)grow * 512 + kh * 256 + cg * 16);
                else          sts_zero16(dst);
            }
        }
        asm volatile("cp.async.commit_group;" ::: "memory");
    };

    prefetchA(0, bufA[0]);

    for (int s = 0; s < nstg; s++) {
        const int p = s & 1;
        __syncthreads();
        {
            int kh = s & 1;
            const char* bsrc = (const char*)Bt + ((size_t)(tile0 + (s >> 1)) * 2 + kh) * 32768;
            #pragma unroll
            for (int i = 0; i < 8; i++) {
                uint32_t t = (uint32_t)(tid + i * 256) * 16u;
                cp_async16(sb + OFF_B + t, bsrc + t);
            }
            asm volatile("cp.async.commit_group;" ::: "memory");
        }
        if (s < 2) {
            // self stage: raw fp32 -> in-place hi/lo bf16 convert
            asm volatile("cp.async.wait_group 1;" ::: "memory");
            #pragma unroll
            for (int h = 0; h < 2; h++) {       // disjoint row halves: 0-63 / 64-127
                float4 raw[4];
                #pragma unroll
                for (int i = 0; i < 4; i++) {
                    int g = h * 1024 + tid + i * 256;
                    raw[i] = lds_f4(bufA[p] + (uint32_t)g * 16u);
                }
                __syncthreads();
                #pragma unroll
                for (int i = 0; i < 4; i++) {
                    int g = h * 1024 + tid + i * 256;
                    int r = g >> 4, cg = g & 15;
                    __nv_bfloat162 h01 = __floats2bfloat162_rn(raw[i].x, raw[i].y);
                    __nv_bfloat162 h23 = __floats2bfloat162_rn(raw[i].z, raw[i].w);
                    float2 f01 = __bfloat1622float2(h01), f23 = __bfloat1622float2(h23);
                    __nv_bfloat162 l01 = __floats2bfloat162_rn(raw[i].x - f01.x, raw[i].y - f01.y);
                    __nv_bfloat162 l23 = __floats2bfloat162_rn(raw[i].z - f23.x, raw[i].w - f23.y);
                    uint32_t base = bufA[p] + (uint32_t)r * 256u
                                  + (uint32_t)((((cg >> 1) ^ (r & 7)) << 4) + ((cg & 1) << 3));
                    sts_u2(base,        bf2u(h01), bf2u(h23));
                    sts_u2(base + 128u, bf2u(l01), bf2u(l23));
                }
            }
        }
        asm volatile("cp.async.wait_group 0;" ::: "memory");
        __syncthreads();
        if (s + 1 < nstg) prefetchA(s + 1, bufA[1 - p]);

        #pragma unroll
        for (int ks = 0; ks < 4; ks++) {
            uint32_t ah[2][4], al[2][4];
            #pragma unroll
            for (int mt = 0; mt < 2; mt++) {
                int r = mw * 32 + mt * 16 + a_rowl;
                uint32_t base = bufA[p] + (uint32_t)r * 256u
                              + (uint32_t)(((2 * ks + a_half) ^ (r & 7)) << 4);
                ldsm_x4(ah[mt], base);
                ldsm_x4(al[mt], base + 128u);
            }
            #pragma unroll
            for (int nb = 0; nb < 4; nb++) {
                int r = nw * 64 + nb * 16 + b_rowl;
                uint32_t base = sb + OFF_B + (uint32_t)r * 256u
                              + (uint32_t)(((2 * ks + b_half) ^ (r & 7)) << 4);
                uint32_t bh[4], bl[4];
                ldsm_x4(bh, base);
                ldsm_x4(bl, base + 128u);
                #pragma unroll
                for (int mt = 0; mt < 2; mt++) {
                    mma_bf16(acc[mt][nb * 2 + 0], ah[mt], bh[0], bh[1]);
                    mma_bf16(acc[mt][nb * 2 + 1], ah[mt], bh[2], bh[3]);
                    mma_bf16(acc[mt][nb * 2 + 0], ah[mt], bl[0], bl[1]);
                    mma_bf16(acc[mt][nb * 2 + 1], ah[mt], bl[2], bl[3]);
                    mma_bf16(acc[mt][nb * 2 + 0], al[mt], bh[0], bh[1]);
                    mma_bf16(acc[mt][nb * 2 + 1], al[mt], bh[2], bh[3]);
                }
            }
        }
    }

    // ---- epilogue: relu(acc+bias) @ Wproj, shfl-reduce, plain store (rows disjoint per block) ----
    const float* bias_s = (const float*)(smem + OFF_BIAS);
    const float* pw = (const float*)(smem + OFF_PW);
    #pragma unroll
    for (int mt = 0; mt < 2; mt++) {
        float p0[4] = {0.f, 0.f, 0.f, 0.f};
        float p1[4] = {0.f, 0.f, 0.f, 0.f};
        #pragma unroll
        for (int nt = 0; nt < 8; nt++) {
            int col = nw * 64 + nt * 8 + (lane & 3) * 2;
            float b0 = bias_s[col], b1v = bias_s[col + 1];
            float vx = fmaxf(acc[mt][nt][0] + b0, 0.f);
            float vy = fmaxf(acc[mt][nt][1] + b1v, 0.f);
            float vz = fmaxf(acc[mt][nt][2] + b0, 0.f);
            float vw = fmaxf(acc[mt][nt][3] + b1v, 0.f);
            #pragma unroll
            for (int c = 0; c < 4; c++) {
                p0[c] += vx * pw[col * 4 + c] + vy * pw[(col + 1) * 4 + c];
                p1[c] += vz * pw[col * 4 + c] + vw * pw[(col + 1) * 4 + c];
            }
        }
        #pragma unroll
        for (int c = 0; c < 4; c++) {
            p0[c] += __shfl_xor_sync(0xffffffffu, p0[c], 1);
            p0[c] += __shfl_xor_sync(0xffffffffu, p0[c], 2);
            p1[c] += __shfl_xor_sync(0xffffffffu, p1[c], 1);
            p1[c] += __shfl_xor_sync(0xffffffffu, p1[c], 2);
        }
        if ((lane & 3) == 0) {
            int r0l = mw * 32 + mt * 16 + (lane >> 2);
            float* buf = (float*)(smem + OFF_A0);      // reuse A buffer for cross-warp combine
            if (nw == 0) {
                #pragma unroll
                for (int c = 0; c < 4; c++) buf[r0l * 4 + c] = p0[c];
                #pragma unroll
                for (int c = 0; c < 4; c++) buf[(r0l + 8) * 4 + c] = p1[c];
            }
        }
        __syncthreads();
        if ((lane & 3) == 0 && nw == 1) {
            int r0l = mw * 32 + mt * 16 + (lane >> 2);
            float* buf = (float*)(smem + OFF_A0);
            int r0 = m0 + r0l;
            if (r0 < M) {
                float q0 = buf[r0l * 4 + 0] + p0[0];
                float q1 = buf[r0l * 4 + 1] + p0[1];
                float q2 = buf[r0l * 4 + 2] + p0[2];
                float q3 = buf[r0l * 4 + 3] + p0[3];
                if (is_app) *(float4*)(papp + (size_t)r0 * 4) = make_float4(q0, q1, q2, q3);
                else        *(float2*)(pattr + (size_t)r0 * 2) = make_float2(q0, q1);
            }
            if (r0 + 8 < M) {
                float q0 = buf[(r0l + 8) * 4 + 0] + p1[0];
                float q1 = buf[(r0l + 8) * 4 + 1] + p1[1];
                float q2 = buf[(r0l + 8) * 4 + 2] + p1[2];
                float q3 = buf[(r0l + 8) * 4 + 3] + p1[3];
                if (is_app) *(float4*)(papp + (size_t)(r0 + 8) * 4) = make_float4(q0, q1, q2, q3);
                else        *(float2*)(pattr + (size_t)(r0 + 8) * 2) = make_float2(q0, q1);
            }
        }
        __syncthreads();
    }
}

// ---------------- fused layer-2 aggregation + finalize (packed CSR, serial per node) ----------------
__global__ void __launch_bounds__(256) final_kernel(float* __restrict__ out)
{
    int v = blockIdx.x * 256 + threadIdx.x;
    if (v >= N_APP) return;
    int g1 = BASE1 + v, g2 = BASE2 + v;
    int2 m1 = __ldg(&g_meta[g1]);
    int n1 = m1.x;
    int s1 = m1.y - n1 + g_bsum[g1 >> 10];
    float a0 = 0.f, a1 = 0.f;
    #pragma unroll 4
    for (int i = 0; i < n1; i++) {
        uint2 rec = __ldg(&g_pack[s1 + i]);
        int sp = (int)rec.x;
        float w = __uint_as_float(rec.y);
        a0 += w * g_pattr[sp * 2 + 0];
        a1 += w * g_pattr[sp * 2 + 1];
    }
    int2 m2 = __ldg(&g_meta[g2]);
    int n2 = m2.x;
    int s2 = m2.y - n2 + g_bsum[g2 >> 10];
    float b0 = 0.f, b1v = 0.f;
    #pragma unroll 4
    for (int i = 0; i < n2; i++) {
        uint2 rec = __ldg(&g_pack[s2 + i]);
        int sp = (int)rec.x;
        float w = __uint_as_float(rec.y);
        b0  += w * g_papp[sp * 4 + 2];
        b1v += w * g_papp[sp * 4 + 3];
    }
    float i1 = 1.f / fmaxf((float)n1, 1.f);
    float i2 = 1.f / fmaxf((float)n2, 1.f);
    out[v * 2 + 0] = g_papp[v * 4 + 0] + a0 * i1 + b0 * i2 + g_bce[0];
    out[v * 2 + 1] = g_papp[v * 4 + 1] + a1 * i1 + b1v * i2 + g_bce[1];
}

// ---------------- launch ----------------
extern "C" void kernel_launch(void* const* d_in, const int* in_sizes, int n_in,
                              void* d_out, int out_size)
{
    const float* x_app   = (const float*)d_in[0];
    const float* x_attr  = (const float*)d_in[1];
    const float* ew0     = (const float*)d_in[2];
    const float* ew1     = (const float*)d_in[3];
    const float* ew2     = (const float*)d_in[4];
    const float* Wself1  = (const float*)d_in[5];
    const float* Wneigh1 = (const float*)d_in[6];
    const float* b1      = (const float*)d_in[7];
    const float* Wself2  = (const float*)d_in[8];
    const float* Wneigh2 = (const float*)d_in[9];
    const float* b2      = (const float*)d_in[10];
    const float* Wc      = (const float*)d_in[11];
    const float* bc      = (const float*)d_in[12];
    const int* src0 = (const int*)d_in[13];
    const int* dst0 = (const int*)d_in[14];
    const int* src1 = (const int*)d_in[15];
    const int* dst1 = (const int*)d_in[16];
    const int* src2 = (const int*)d_in[17];
    const int* dst2 = (const int*)d_in[18];
    float* out = (float*)d_out;
    const int E = in_sizes[2];

    float *pattr, *papp, *bsum1, *Wn1c, *Wapp4;
    int2 *meta;
    uint2 *Bt, *s0, *s1, *s2;
    cudaGetSymbolAddress((void**)&s0, g_s0);
    cudaGetSymbolAddress((void**)&s1, g_s1);
    cudaGetSymbolAddress((void**)&s2, g_s2);
    cudaGetSymbolAddress((void**)&pattr, g_pattr);
    cudaGetSymbolAddress((void**)&papp, g_papp);
    cudaGetSymbolAddress((void**)&meta, g_meta);
    cudaGetSymbolAddress((void**)&bsum1, g_bsum1);
    cudaGetSymbolAddress((void**)&Wn1c, g_Wn1c);
    cudaGetSymbolAddress((void**)&Wapp4, g_Wapp4);
    cudaGetSymbolAddress((void**)&Bt, g_Bt);

    cudaFuncSetAttribute(gemm_fused_all, cudaFuncAttributeMaxDynamicSharedMemorySize, GEMM_SMEM);

    cudaMemsetAsync(meta, 0, sizeof(g_meta), 0);

    // fused: edge counting + weight prep (+ scan counter reset) in one launch
    int eb3 = (3 * E + 255) / 256;
    count_prep_kernel<<<eb3 + 6, 256>>>(dst0, dst1, dst2, E, eb3,
                                        Wself1, Wneigh1, b1, Wself2, Wneigh2, b2, Wc, bc);
    scan_kernel<<<NBLK_SCAN, 256>>>();
    fill_kernel<<<eb3, 256>>>(dst0, dst1, dst2, src0, src1, src2, ew0, ew1, ew2, E);

    // layer-1 aggregation: contiguous packed reads, pre-scaled pre-split bf16 output
    agg_kernel<<<(N_TOT * 32 + 255) / 256, 256>>>(
        (const float4*)x_app, (const float4*)x_attr);

    // merged layer-1 GEMMs + fused layer-2 projection (plain-store epilogue)
    gemm_fused_all<<<NB_ATTR + NB_APP, 256, GEMM_SMEM>>>(
        x_attr, x_app, (const char*)s0, (const char*)s1, (const char*)s2,
        b1, bsum1, Wn1c, Wapp4, Bt, pattr, papp);

    // fused layer-2 aggregation + classify
    final_kernel<<<(N_APP + 255) / 256, 256>>>(out);
}